// round 6
// baseline (speedup 1.0000x reference)
#include <cuda_runtime.h>

#define BB 8
#define NN 9216
#define FF 1024
#define KK 4096

// Scratch (device globals; zero at module load; every call restores invariants)
__device__ int  g_hist[BB * KK];    // per-batch voxel histogram (zero on entry)
__device__ int  g_off[BB * KK];     // scatter cursor per voxel
__device__ int2 g_slotSC[BB * KK];  // per output slot (rank): {start, count}
__device__ int  g_sorted[BB * NN];  // point indices grouped by voxel
__device__ int  g_count[BB];        // occupied voxels per batch
__device__ int  g_done[BB];         // hist-complete counter per batch (resets to 0)
__device__ int  g_scan_done[BB];    // scan-complete flag per batch (resets to 0)
__device__ int  g_fin[BB];          // scatter-complete counter per batch (resets to 0)

// Compact voxel id: cx*256+cy*16+cz preserves the reference HASH_M=1024
// lexicographic ordering; the per-batch min subtraction is a constant per-axis
// shift and changes neither grouping nor order, hence ranks are unchanged.
__device__ __forceinline__ int voxel_id(const float* __restrict__ bx, int i) {
    float x = bx[i * 3 + 0];
    float y = bx[i * 3 + 1];
    float z = bx[i * 3 + 2];
    int cx = (int)floorf(__fdiv_rn(x, 0.2f));
    int cy = (int)floorf(__fdiv_rn(y, 0.2f));
    int cz = (int)floorf(__fdiv_rn(z, 0.2f));
    cx = min(max(cx, 0), 15);
    cy = min(max(cy, 0), 15);
    cz = min(max(cz, 0), 15);
    return (cx << 8) | (cy << 4) | cz;
}

// Fused build, grid (10, BB) x 256. Per batch: blocks x=0..8 histogram their
// 1024 points (ids held in registers), signal g_done[b]; block x=9 waits,
// scans, signals g_scan_done[b]; blocks x=0..8 then counting-sort scatter.
// Only per-batch handshakes (no grid-wide barrier); 80 blocks co-resident.
__global__ __launch_bounds__(256) void build_kernel(const float* __restrict__ xyz) {
    const int b = blockIdx.y;
    const int tid = threadIdx.x;

    if (blockIdx.x < 9) {
        // ---- hist blocks ----
        const float* bx = xyz + (size_t)b * NN * 3;
        int vid[4], pid[4];
#pragma unroll
        for (int j = 0; j < 4; j++) {
            int i = blockIdx.x * 1024 + tid + j * 256;  // 9*1024 == NN exactly
            pid[j] = i;
            vid[j] = voxel_id(bx, i);
            atomicAdd(&g_hist[b * KK + vid[j]], 1);
        }
        __syncthreads();
        if (tid == 0) {
            __threadfence();
            atomicAdd(&g_done[b], 1);
            // wait for this batch's scan
            while (*((volatile int*)&g_scan_done[b]) == 0) {}
            __threadfence();
        }
        __syncthreads();

        // ---- scatter from register-held ids ----
#pragma unroll
        for (int j = 0; j < 4; j++) {
            int pos = atomicAdd(&g_off[b * KK + vid[j]], 1);
            g_sorted[b * NN + pos] = pid[j];
        }
        __syncthreads();
        if (tid == 0) {
            int f = atomicAdd(&g_fin[b], 1);
            if (f == 8) {  // last scatter block: reset flags for graph replay
                g_scan_done[b] = 0;
                __threadfence();
                g_fin[b] = 0;
            }
        }
    } else {
        // ---- scan block: packed dual exclusive scan over 4096 bins ----
        // low 16 bits: point-count prefix (<=9216<2^16); high bits: occupancy
        // prefix == compacted rank. 256 threads x 16 bins.
        __shared__ int wsum[8];

        // zero the slot table while hist blocks work (empty ranks => zero rows)
        {
            int2 z = make_int2(0, 0);
#pragma unroll
            for (int j = 0; j < 16; j++) g_slotSC[b * KK + tid * 16 + j] = z;
        }

        if (tid == 0) {
            while (*((volatile int*)&g_done[b]) < 9) {}
            __threadfence();
        }
        __syncthreads();

        const int base = tid * 16;
        int cnts[16], e[16];
        int ts = 0;
#pragma unroll
        for (int j = 0; j < 16; j++) {
            int c = g_hist[b * KK + base + j];
            cnts[j] = c;
            e[j] = c | ((c > 0) << 16);
            ts += e[j];
        }

        const int lane = tid & 31;
        const int wid = tid >> 5;

        int incl = ts;
#pragma unroll
        for (int off = 1; off < 32; off <<= 1) {
            int n = __shfl_up_sync(0xffffffffu, incl, off);
            if (lane >= off) incl += n;
        }
        if (lane == 31) wsum[wid] = incl;
        __syncthreads();

        if (wid == 0 && lane < 8) {
            int wv = wsum[lane];
            int wi = wv;
#pragma unroll
            for (int off = 1; off < 8; off <<= 1) {
                int n = __shfl_up_sync(0xffu, wi, off);
                if (lane >= off) wi += n;
            }
            wsum[lane] = wi - wv;
            if (lane == 7) g_count[b] = (wi >> 16);
        }
        __syncthreads();

        int pref = wsum[wid] + (incl - ts);  // exclusive prefix for this thread
#pragma unroll
        for (int j = 0; j < 16; j++) {
            int start = pref & 0xFFFF;
            int rank = pref >> 16;
            if (cnts[j] > 0) g_slotSC[b * KK + rank] = make_int2(start, cnts[j]);
            g_off[b * KK + base + j] = start;  // scatter cursor (by voxel id)
            g_hist[b * KK + base + j] = 0;     // restore zero-invariant
            pref += e[j];
        }
        __syncthreads();
        if (tid == 0) {
            g_done[b] = 0;  // reset for next replay
            __threadfence();
            g_scan_done[b] = 1;  // release scatter blocks
        }
    }
}

// Pool: one block per TWO output rows. 256 threads x float4 = one 4KB row.
// Per-warp coalesced index load + shuffle broadcast -> all cnt feature loads
// independent; streaming loads/stores (zero reuse anywhere).
// Block (0,0) also writes the batch_offset tail.
__global__ __launch_bounds__(256) void pool_kernel(const float* __restrict__ feat,
                                                   float* __restrict__ out,
                                                   float* __restrict__ out_tail) {
    const int b = blockIdx.y;
    const int t = threadIdx.x;
    const int lane = t & 31;
    const float4* fb = reinterpret_cast<const float4*>(feat) + (size_t)b * NN * (FF / 4);

    if (out_tail != nullptr && blockIdx.x == 0 && b == 0 && t == 0) {
        int acc = 0;
#pragma unroll
        for (int i = 0; i < BB; i++) {
            acc += g_count[i];
            out_tail[i] = (float)acc;
        }
    }

    const int slot0 = b * KK + blockIdx.x * 2;
    const int2 sc0 = g_slotSC[slot0];
    const int2 sc1 = g_slotSC[slot0 + 1];

#pragma unroll
    for (int s = 0; s < 2; s++) {
        const int slot = slot0 + s;
        const int2 sc = (s == 0) ? sc0 : sc1;
        float4* o = reinterpret_cast<float4*>(out) + (size_t)slot * (FF / 4);
        const int cnt = sc.y;
        if (cnt == 0) {
            __stcs(&o[t], make_float4(0.f, 0.f, 0.f, 0.f));
            continue;
        }

        const int* sp = g_sorted + b * NN + sc.x;
        float4 acc = make_float4(0.f, 0.f, 0.f, 0.f);
        for (int base = 0; base < cnt; base += 32) {
            int m = min(32, cnt - base);
            int myidx = (lane < m) ? sp[base + lane] : 0;
#pragma unroll 4
            for (int j = 0; j < m; j++) {
                int idx = __shfl_sync(0xffffffffu, myidx, j);
                float4 v = __ldcs(&fb[(size_t)idx * (FF / 4) + t]);
                acc.x += v.x; acc.y += v.y; acc.z += v.z; acc.w += v.w;
            }
        }

        float inv = 1.0f / (float)cnt;
        __stcs(&o[t], make_float4(acc.x * inv, acc.y * inv, acc.z * inv, acc.w * inv));
    }
}

extern "C" void kernel_launch(void* const* d_in, const int* in_sizes, int n_in,
                              void* d_out, int out_size) {
    const float* features = (const float*)d_in[0];
    const float* xyz = (const float*)d_in[1];
    if (n_in >= 2 && in_sizes[0] < in_sizes[1]) {
        features = (const float*)d_in[1];
        xyz = (const float*)d_in[0];
    }
    float* out = (float*)d_out;
    float* tail = (out_size > BB * KK * FF) ? out + (size_t)BB * KK * FF : nullptr;

    dim3 gbuild(10, BB);
    build_kernel<<<gbuild, 256>>>(xyz);
    dim3 gpool(KK / 2, BB);
    pool_kernel<<<gpool, 256>>>(features, out, tail);
}